// round 10
// baseline (speedup 1.0000x reference)
#include <cuda_runtime.h>

#define N_NODES 20000
#define N_EDGES 640000
#define D 128
#define NBLK 148          // 1 block/SM -> co-residency guaranteed for grid barrier
#define NTHR 1024
#define WTICKETS 5000     // 4 nodes per warp-ticket; 5000*4 == N_NODES exactly
#define XPAD 132          // Xw row stride (floats): 16B-aligned, bank-skewed

// ---- scratch (no allocations). .bss zero-init. All mutable globals return to
// a deterministic state each run (sense read at kernel start, counters reset
// by barrier completers), so graph replays are safe. ----
__device__ int      g_deg[N_NODES];
__device__ int      g_cursor[N_NODES];
__device__ int      g_rowstart[N_NODES + 1];
__device__ int      g_csr[N_EDGES];
__device__ float    g_h0[N_NODES * D];
__device__ float    g_h1[N_NODES * D];
__device__ float    g_h2[N_NODES * D];
__device__ unsigned g_bar_count;
__device__ unsigned g_bar_sense;
__device__ int      g_tile_ctr[4];

struct SMem {
    float Xs[32][4][XPAD];  // 66 KB : per-warp private 4-row staging (padded)
    float Wf[128][128];     // 64 KB : full W, block-shared, resident per layer
};

// ---- packed f32x2 helpers (FFMA2/FADD2 — not emitted by ptxas from C++) ----
typedef unsigned long long ull;
__device__ __forceinline__ ull f2_pack(float x) {
    ull r; asm("mov.b64 %0,{%1,%1};" : "=l"(r) : "f"(x)); return r;
}
__device__ __forceinline__ ull f2_add(ull a, ull b) {
    ull d; asm("add.rn.f32x2 %0,%1,%2;" : "=l"(d) : "l"(a), "l"(b)); return d;
}
__device__ __forceinline__ ull f2_fma(ull a, ull b, ull c) {
    ull d; asm("fma.rn.f32x2 %0,%1,%2,%3;" : "=l"(d) : "l"(a), "l"(b), "l"(c)); return d;
}

// sense-reversing grid barrier; all NBLK blocks co-resident (1/SM).
__device__ __forceinline__ void grid_barrier(unsigned& sense, int* reset_ctr) {
    __syncthreads();
    sense ^= 1u;
    if (threadIdx.x == 0) {
        __threadfence();
        unsigned arrived = atomicAdd(&g_bar_count, 1u);
        if (arrived == NBLK - 1) {
            g_bar_count = 0;
            if (reset_ctr) *reset_ctr = 0;
            __threadfence();
            atomicExch(&g_bar_sense, sense);
        } else {
            while (atomicAdd(&g_bar_sense, 0u) != sense) __nanosleep(64);
        }
    }
    __syncthreads();
}

// ---------------------------------------------------------------------------
// one fused layer, warp-autonomous: each warp pulls 4-node tickets, gathers
// into its private smem slice (MLP 32, packed adds), then GEMMs against the
// block-shared W with packed FFMA2.
__device__ __forceinline__ void do_layer(
    SMem& sm,
    const float* __restrict__ hin,
    const float* __restrict__ W,
    const float* __restrict__ bias,
    float* __restrict__ hout,
    int* ticket_ctr)
{
    const int tid  = threadIdx.x;
    const int lane = tid & 31;
    const int wid  = tid >> 5;
    const ulonglong2* __restrict__ hv = (const ulonglong2*)hin;  // 32 per row

    // ---- load full W into smem (4096 float4 / 1024 threads = 4 each) ----
#pragma unroll
    for (int i = 0; i < 4; i++) {
        int idx = tid + i * NTHR;
        int k   = idx >> 5;
        int c4  = (idx & 31) * 4;
        *(float4*)&sm.Wf[k][c4] = __ldg((const float4*)&W[k * 128 + c4]);
    }
    __syncthreads();

    float (*Xw)[XPAD] = sm.Xs[wid];
    const int half = lane >> 4;                // 0/1 : rows {0,1} vs {2,3}
    const int li   = lane & 15;
    const int cb   = li * 8;                   // 8 output columns per lane
    const int r0   = half * 2;

    const ulonglong2 bA = *(const ulonglong2*)&bias[cb];
    const ulonglong2 bB = *(const ulonglong2*)&bias[cb + 4];

    for (;;) {
        int t;
        if (lane == 0) t = atomicAdd(ticket_ctr, 1);
        t = __shfl_sync(0xffffffffu, t, 0);
        if (t >= WTICKETS) break;
        const int node0 = t * 4;

        // ---- gather 4 node rows (32 edges in flight, packed adds) ----
#pragma unroll
        for (int n = 0; n < 4; n++) {
            int node = node0 + n;
            ulonglong2 s = hv[node * 32 + lane];
            ull a0 = s.x, a1 = s.y;            // even-edge chain
            ull b0 = 0ull, b1 = 0ull;          // odd-edge chain
            int beg = g_rowstart[node];
            int end = g_rowstart[node + 1];
            for (int k = beg; k < end; k += 32) {
                int kk  = k + lane;
                int myj = (kk < end) ? g_csr[kk] : -1;
#pragma unroll
                for (int e = 0; e < 32; e += 2) {
                    int j0 = __shfl_sync(0xffffffffu, myj, e);
                    int j1 = __shfl_sync(0xffffffffu, myj, e + 1);
                    if (j0 >= 0) {
                        ulonglong2 v = hv[j0 * 32 + lane];
                        a0 = f2_add(a0, v.x); a1 = f2_add(a1, v.y);
                    }
                    if (j1 >= 0) {
                        ulonglong2 v = hv[j1 * 32 + lane];
                        b0 = f2_add(b0, v.x); b1 = f2_add(b1, v.y);
                    }
                }
            }
            a0 = f2_add(a0, b0); a1 = f2_add(a1, b1);
            ulonglong2 o; o.x = a0; o.y = a1;
            *(ulonglong2*)&Xw[n][lane * 4] = o;
        }
        __syncwarp();

        // ---- GEMM: hout[node0+r0 : +2, cb:cb+8] = Xw @ Wf + b (FFMA2) ----
        ull A[2][4];
#pragma unroll
        for (int r = 0; r < 2; r++)
#pragma unroll
            for (int c = 0; c < 4; c++) A[r][c] = 0ull;

#pragma unroll 8
        for (int k = 0; k < 128; k++) {
            ull xd0 = f2_pack(Xw[r0][k]);
            ull xd1 = f2_pack(Xw[r0 + 1][k]);
            ulonglong2 wa = *(const ulonglong2*)&sm.Wf[k][cb];
            ulonglong2 wb = *(const ulonglong2*)&sm.Wf[k][cb + 4];
            A[0][0] = f2_fma(xd0, wa.x, A[0][0]);
            A[0][1] = f2_fma(xd0, wa.y, A[0][1]);
            A[0][2] = f2_fma(xd0, wb.x, A[0][2]);
            A[0][3] = f2_fma(xd0, wb.y, A[0][3]);
            A[1][0] = f2_fma(xd1, wa.x, A[1][0]);
            A[1][1] = f2_fma(xd1, wa.y, A[1][1]);
            A[1][2] = f2_fma(xd1, wb.x, A[1][2]);
            A[1][3] = f2_fma(xd1, wb.y, A[1][3]);
        }

#pragma unroll
        for (int r = 0; r < 2; r++) {
            int row = node0 + r0 + r;
            ulonglong2 o0, o1;
            o0.x = f2_add(A[r][0], bA.x); o0.y = f2_add(A[r][1], bA.y);
            o1.x = f2_add(A[r][2], bB.x); o1.y = f2_add(A[r][3], bB.y);
            *(ulonglong2*)&hout[(long)row * D + cb]     = o0;
            *(ulonglong2*)&hout[(long)row * D + cb + 4] = o1;
        }
        __syncwarp();   // Xw reads done before next ticket's gather writes
    }
}

// ---------------------------------------------------------------------------
__global__ __launch_bounds__(NTHR) void gin_persistent_kernel(
    const float* __restrict__ h,
    const int*   __restrict__ ei,
    const float* __restrict__ W0, const float* __restrict__ b0,
    const float* __restrict__ W1, const float* __restrict__ b1,
    const float* __restrict__ W2, const float* __restrict__ b2,
    const float* __restrict__ W3, const float* __restrict__ b3,
    float* __restrict__ out)
{
    extern __shared__ char smem_raw[];
    SMem& sm = *reinterpret_cast<SMem*>(smem_raw);
    const int tid = threadIdx.x;

    unsigned sense = *(volatile unsigned*)&g_bar_sense;   // parity-agnostic

    // ---- Phase 1: count in-degrees (g_deg is 0 on entry) ----
    for (int e = blockIdx.x * NTHR + tid; e < N_EDGES; e += NBLK * NTHR)
        atomicAdd(&g_deg[ei[N_EDGES + e]], 1);
    grid_barrier(sense, nullptr);

    // ---- Phase 2: exclusive scan (block 0 only), reset deg/cursor ----
    if (blockIdx.x == 0) {
        int* partial = (int*)sm.Xs;
        const int CH = (N_NODES + NTHR - 1) / NTHR;        // 20
        const int base = tid * CH;

        int s = 0;
        for (int j = 0; j < CH; j++) {
            int idx = base + j;
            if (idx < N_NODES) s += g_deg[idx];
        }
        partial[tid] = s;
        __syncthreads();
        for (int off = 1; off < NTHR; off <<= 1) {
            int v = 0;
            if (tid >= off) v = partial[tid - off];
            __syncthreads();
            if (tid >= off) partial[tid] += v;
            __syncthreads();
        }
        int run = (tid > 0) ? partial[tid - 1] : 0;
        for (int j = 0; j < CH; j++) {
            int idx = base + j;
            if (idx < N_NODES) {
                g_rowstart[idx] = run;
                run += g_deg[idx];
                g_deg[idx]    = 0;
                g_cursor[idx] = 0;
            }
        }
        if (tid == NTHR - 1) g_rowstart[N_NODES] = partial[NTHR - 1];
        __syncthreads();
    }
    grid_barrier(sense, nullptr);

    // ---- Phase 3: fill CSR ----
    for (int e = blockIdx.x * NTHR + tid; e < N_EDGES; e += NBLK * NTHR) {
        int s = ei[e];
        int d = ei[N_EDGES + e];
        int pos = atomicAdd(&g_cursor[d], 1);
        g_csr[g_rowstart[d] + pos] = s;
    }
    grid_barrier(sense, nullptr);

    // ---- Phases 4-7: the four GIN layers ----
    do_layer(sm, h,    W0, b0, g_h0, &g_tile_ctr[0]);
    grid_barrier(sense, &g_tile_ctr[0]);
    do_layer(sm, g_h0, W1, b1, g_h1, &g_tile_ctr[1]);
    grid_barrier(sense, &g_tile_ctr[1]);
    do_layer(sm, g_h1, W2, b2, g_h2, &g_tile_ctr[2]);
    grid_barrier(sense, &g_tile_ctr[2]);
    do_layer(sm, g_h2, W3, b3, out,  &g_tile_ctr[3]);
    grid_barrier(sense, &g_tile_ctr[3]);
}

// ---------------------------------------------------------------------------
extern "C" void kernel_launch(void* const* d_in, const int* in_sizes, int n_in,
                              void* d_out, int out_size) {
    const float* h  = (const float*)d_in[0];
    const int*   ei = (const int*)d_in[1];

    cudaFuncSetAttribute(gin_persistent_kernel,
                         cudaFuncAttributeMaxDynamicSharedMemorySize,
                         (int)sizeof(SMem));

    gin_persistent_kernel<<<NBLK, NTHR, sizeof(SMem)>>>(
        h, ei,
        (const float*)d_in[2], (const float*)d_in[3],
        (const float*)d_in[4], (const float*)d_in[5],
        (const float*)d_in[6], (const float*)d_in[7],
        (const float*)d_in[8], (const float*)d_in[9],
        (float*)d_out);
}

// round 11
// speedup vs baseline: 1.3842x; 1.3842x over previous
#include <cuda_runtime.h>

#define N_NODES 20000
#define N_EDGES 640000
#define D 128
#define NBLK 148          // 1 block/SM -> co-residency guaranteed for grid barrier
#define NTHR 1024
#define WTICKETS 5000     // 4 nodes per warp-ticket; 5000*4 == N_NODES exactly

// ---- scratch (no allocations). .bss zero-init. All mutable globals return to
// a deterministic state each run (sense read at kernel start, counters reset
// by barrier completers), so graph replays are safe. ----
__device__ int      g_deg[N_NODES];
__device__ int      g_cursor[N_NODES];
__device__ int      g_rowstart[N_NODES + 1];
__device__ int      g_csr[N_EDGES];
__device__ float    g_h0[N_NODES * D];
__device__ float    g_h1[N_NODES * D];
__device__ float    g_h2[N_NODES * D];
__device__ unsigned g_bar_count;
__device__ unsigned g_bar_sense;
__device__ int      g_tile_ctr[4];

struct SMem {
    float Xs[32][4][128];  // 64 KB : per-warp private 4-row staging (R9 layout)
    float Wf[128][128];    // 64 KB : full W, block-shared, resident per layer
};

// ---- packed f32x2 helpers ----
typedef unsigned long long ull;
__device__ __forceinline__ ull f2_pack(float x) {
    ull r; asm("mov.b64 %0,{%1,%1};" : "=l"(r) : "f"(x)); return r;
}
__device__ __forceinline__ ull f2_add(ull a, ull b) {
    ull d; asm("add.rn.f32x2 %0,%1,%2;" : "=l"(d) : "l"(a), "l"(b)); return d;
}
__device__ __forceinline__ ull f2_fma(ull a, ull b, ull c) {
    ull d; asm("fma.rn.f32x2 %0,%1,%2,%3;" : "=l"(d) : "l"(a), "l"(b), "l"(c)); return d;
}

// sense-reversing grid barrier; all NBLK blocks co-resident (1/SM).
__device__ __forceinline__ void grid_barrier(unsigned& sense, int* reset_ctr) {
    __syncthreads();
    sense ^= 1u;
    if (threadIdx.x == 0) {
        __threadfence();
        unsigned arrived = atomicAdd(&g_bar_count, 1u);
        if (arrived == NBLK - 1) {
            g_bar_count = 0;
            if (reset_ctr) *reset_ctr = 0;
            __threadfence();
            atomicExch(&g_bar_sense, sense);
        } else {
            while (atomicAdd(&g_bar_sense, 0u) != sense) __nanosleep(64);
        }
    }
    __syncthreads();
}

// ---------------------------------------------------------------------------
// one fused layer, warp-autonomous (R9 structure). Gather identical to R9;
// GEMM keeps R9's LDS pattern but does the math with packed FFMA2.
__device__ __forceinline__ void do_layer(
    SMem& sm,
    const float* __restrict__ hin,
    const float* __restrict__ W,
    const float* __restrict__ bias,
    float* __restrict__ hout,
    int* ticket_ctr)
{
    const int tid  = threadIdx.x;
    const int lane = tid & 31;
    const int wid  = tid >> 5;
    const float4* __restrict__ hv = (const float4*)hin;

    // ---- load full W into smem (4096 float4 / 1024 threads = 4 each) ----
#pragma unroll
    for (int i = 0; i < 4; i++) {
        int idx = tid + i * NTHR;
        int k   = idx >> 5;
        int c4  = (idx & 31) * 4;
        *(float4*)&sm.Wf[k][c4] = __ldg((const float4*)&W[k * 128 + c4]);
    }
    __syncthreads();

    float (*Xw)[128] = sm.Xs[wid];
    const int cb = lane * 4;                   // lane's 4 output columns
    const ulonglong2 bv = *(const ulonglong2*)&bias[cb];   // 2 packed col-pairs

    for (;;) {
        int t;
        if (lane == 0) t = atomicAdd(ticket_ctr, 1);
        t = __shfl_sync(0xffffffffu, t, 0);
        if (t >= WTICKETS) break;
        const int node0 = t * 4;

        // ---- gather 4 node rows (16 edges in flight per warp) — R9 exact ----
#pragma unroll
        for (int n = 0; n < 4; n++) {
            int node = node0 + n;
            float4 a = hv[node * 32 + lane];
            int beg = g_rowstart[node];
            int end = g_rowstart[node + 1];
            for (int k = beg; k < end; k += 16) {
                int kk = k + (lane & 15);
                int myj = (kk < end) ? g_csr[kk] : -1;
#pragma unroll
                for (int e = 0; e < 16; e++) {
                    int j = __shfl_sync(0xffffffffu, myj, e);
                    if (j >= 0) {
                        float4 v = hv[j * 32 + lane];
                        a.x += v.x; a.y += v.y; a.z += v.z; a.w += v.w;
                    }
                }
            }
            *(float4*)&Xw[n][lane * 4] = a;
        }
        __syncwarp();

        // ---- GEMM: hout[node0:node0+4, cb:cb+4] = Xw @ Wf + b ----
        // LDS pattern == R9 (xf broadcast LDS.128, W 16B/lane LDS.128);
        // math packed: per k = 4 packs (ALU) + 8 FFMA2 (vs 16 FFMA).
        ull A[4][2];
#pragma unroll
        for (int r = 0; r < 4; r++) { A[r][0] = 0ull; A[r][1] = 0ull; }

#pragma unroll 2
        for (int k = 0; k < 128; k += 4) {
            float4 xf[4];
#pragma unroll
            for (int r = 0; r < 4; r++)
                xf[r] = *(const float4*)&Xw[r][k];     // warp-broadcast
#pragma unroll
            for (int kk = 0; kk < 4; kk++) {
                ulonglong2 w2 = *(const ulonglong2*)&sm.Wf[k + kk][cb];
#pragma unroll
                for (int r = 0; r < 4; r++) {
                    float xv = (kk == 0) ? xf[r].x : (kk == 1) ? xf[r].y
                             : (kk == 2) ? xf[r].z : xf[r].w;
                    ull xp = f2_pack(xv);
                    A[r][0] = f2_fma(xp, w2.x, A[r][0]);
                    A[r][1] = f2_fma(xp, w2.y, A[r][1]);
                }
            }
        }

#pragma unroll
        for (int r = 0; r < 4; r++) {
            ulonglong2 o;
            o.x = f2_add(A[r][0], bv.x);
            o.y = f2_add(A[r][1], bv.y);
            *(ulonglong2*)&hout[(long)(node0 + r) * D + cb] = o;
        }
        __syncwarp();   // Xw reads done before next ticket's gather writes
    }
}

// ---------------------------------------------------------------------------
__global__ __launch_bounds__(NTHR) void gin_persistent_kernel(
    const float* __restrict__ h,
    const int*   __restrict__ ei,
    const float* __restrict__ W0, const float* __restrict__ b0,
    const float* __restrict__ W1, const float* __restrict__ b1,
    const float* __restrict__ W2, const float* __restrict__ b2,
    const float* __restrict__ W3, const float* __restrict__ b3,
    float* __restrict__ out)
{
    extern __shared__ char smem_raw[];
    SMem& sm = *reinterpret_cast<SMem*>(smem_raw);
    const int tid = threadIdx.x;

    unsigned sense = *(volatile unsigned*)&g_bar_sense;   // parity-agnostic

    // ---- Phase 1: count in-degrees (g_deg is 0 on entry) ----
    for (int e = blockIdx.x * NTHR + tid; e < N_EDGES; e += NBLK * NTHR)
        atomicAdd(&g_deg[ei[N_EDGES + e]], 1);
    grid_barrier(sense, nullptr);

    // ---- Phase 2: exclusive scan (block 0 only), reset deg/cursor ----
    if (blockIdx.x == 0) {
        int* partial = (int*)sm.Xs;
        const int CH = (N_NODES + NTHR - 1) / NTHR;        // 20
        const int base = tid * CH;

        int s = 0;
        for (int j = 0; j < CH; j++) {
            int idx = base + j;
            if (idx < N_NODES) s += g_deg[idx];
        }
        partial[tid] = s;
        __syncthreads();
        for (int off = 1; off < NTHR; off <<= 1) {
            int v = 0;
            if (tid >= off) v = partial[tid - off];
            __syncthreads();
            if (tid >= off) partial[tid] += v;
            __syncthreads();
        }
        int run = (tid > 0) ? partial[tid - 1] : 0;
        for (int j = 0; j < CH; j++) {
            int idx = base + j;
            if (idx < N_NODES) {
                g_rowstart[idx] = run;
                run += g_deg[idx];
                g_deg[idx]    = 0;
                g_cursor[idx] = 0;
            }
        }
        if (tid == NTHR - 1) g_rowstart[N_NODES] = partial[NTHR - 1];
        __syncthreads();
    }
    grid_barrier(sense, nullptr);

    // ---- Phase 3: fill CSR ----
    for (int e = blockIdx.x * NTHR + tid; e < N_EDGES; e += NBLK * NTHR) {
        int s = ei[e];
        int d = ei[N_EDGES + e];
        int pos = atomicAdd(&g_cursor[d], 1);
        g_csr[g_rowstart[d] + pos] = s;
    }
    grid_barrier(sense, nullptr);

    // ---- Phases 4-7: the four GIN layers ----
    do_layer(sm, h,    W0, b0, g_h0, &g_tile_ctr[0]);
    grid_barrier(sense, &g_tile_ctr[0]);
    do_layer(sm, g_h0, W1, b1, g_h1, &g_tile_ctr[1]);
    grid_barrier(sense, &g_tile_ctr[1]);
    do_layer(sm, g_h1, W2, b2, g_h2, &g_tile_ctr[2]);
    grid_barrier(sense, &g_tile_ctr[2]);
    do_layer(sm, g_h2, W3, b3, out,  &g_tile_ctr[3]);
    grid_barrier(sense, &g_tile_ctr[3]);
}

// ---------------------------------------------------------------------------
extern "C" void kernel_launch(void* const* d_in, const int* in_sizes, int n_in,
                              void* d_out, int out_size) {
    const float* h  = (const float*)d_in[0];
    const int*   ei = (const int*)d_in[1];

    cudaFuncSetAttribute(gin_persistent_kernel,
                         cudaFuncAttributeMaxDynamicSharedMemorySize,
                         (int)sizeof(SMem));

    gin_persistent_kernel<<<NBLK, NTHR, sizeof(SMem)>>>(
        h, ei,
        (const float*)d_in[2], (const float*)d_in[3],
        (const float*)d_in[4], (const float*)d_in[5],
        (const float*)d_in[6], (const float*)d_in[7],
        (const float*)d_in[8], (const float*)d_in[9],
        (float*)d_out);
}